// round 8
// baseline (speedup 1.0000x reference)
#include <cuda_runtime.h>
#include <cstdint>

#define BB      1024
#define MAXLEN  200
#define FF      64
#define DD      64
#define NT      256
#define RPW     25                         // rows per warp
#define KUNITS  ((MAXLEN * DD * 4) / 16)   // 3200 16-byte units for full k tile
#define SMEM_FLOATS (MAXLEN * DD + 16 * DD + DD + DD + DD + 16)
#define SMEM_BYTES  (SMEM_FLOATS * 4)

__device__ __forceinline__ void cp_async16(uint32_t saddr, const void* gaddr) {
    asm volatile("cp.async.cg.shared.global [%0], [%1], 16;" :: "r"(saddr), "l"(gaddr) : "memory");
}
__device__ __forceinline__ void cp_commit() {
    asm volatile("cp.async.commit_group;" ::: "memory");
}
__device__ __forceinline__ void cp_wait_all() {
    asm volatile("cp.async.wait_group 0;" ::: "memory");
}
__device__ __forceinline__ float fast_sigmoid(float x) {
    float t;
    asm("tanh.approx.f32 %0, %1;" : "=f"(t) : "f"(0.5f * x));
    return fmaf(0.5f, t, 0.5f);
}
__device__ __forceinline__ float fast_exp8(float x) {   // exp(x/8)
    float e;
    asm("ex2.approx.f32 %0, %1;" : "=f"(e) : "f"(x * 0.18033688011112042f));
    return e;
}

__global__ __launch_bounds__(NT, 4)
void attn_kernel(const float* __restrict__ q,
                 const float* __restrict__ k,
                 const int*   __restrict__ kes_length,
                 const float* __restrict__ fs,
                 const float* __restrict__ bias,
                 const float* __restrict__ Wq,
                 const float* __restrict__ Wk,
                 const float* __restrict__ Wv,
                 float*       __restrict__ out) {
    extern __shared__ float smd[];
    float* kbuf  = smd;                       // 12800 floats : full k tile
    float* spart = kbuf + MAXLEN * DD;        // 16*64 partials
    float* squ   = spart + 16 * DD;           // qbar
    float* stmp  = squ + DD;                  // qbar @ Wq
    float* su    = stmp + DD;                 // u, then w
    float* swr   = su + DD;                   // 16 exp-sums

    const int b    = blockIdx.x;
    const int tid  = threadIdx.x;
    const int lane = tid & 31;
    const int warp = tid >> 5;           // 0..7
    const int half = lane >> 4;          // 0/1
    const int hw   = tid >> 4;           // half-warp id 0..15
    const int l16  = tid & 15;

    const float* kb = k + (size_t)b * MAXLEN * DD;

    // ---- stage ENTIRE k[b] tile up-front: one burst, one group ----
    {
        const uint32_t sbk = (uint32_t)__cvta_generic_to_shared(kbuf);
        const char* gk = (const char*)kb;
#pragma unroll
        for (int r = 0; r < 12; ++r) {
            int u = tid + r * NT;
            cp_async16(sbk + u * 16, gk + (size_t)u * 16);
        }
        if (tid < KUNITS - 12 * NT)      // 3200 - 3072 = 128 remainder
            cp_async16(sbk + (tid + 12 * NT) * 16, gk + (size_t)(tid + 12 * NT) * 16);
        cp_commit();
    }

    // ---- qbar[d] = sum_f fs[f] * q[b,f,d]  (float4, 16-way f split) ----
    {
        const float4* qb4 = (const float4*)(q + (size_t)b * FF * DD);
        float4 a = make_float4(0.f, 0.f, 0.f, 0.f);
#pragma unroll
        for (int fi = 0; fi < 4; ++fi) {
            int f = hw + 16 * fi;
            float s = fs[f];
            float4 v = qb4[f * 16 + l16];
            a.x += s * v.x; a.y += s * v.y; a.z += s * v.z; a.w += s * v.w;
        }
        ((float4*)spart)[hw * 16 + l16] = a;
    }
    __syncthreads();
    if (tid < DD) {
        float s = 0.f;
#pragma unroll
        for (int i = 0; i < 16; ++i) s += spart[i * DD + tid];
        squ[tid] = s;
    }
    __syncthreads();

    // ---- tmp[e] = sum_c qbar[c] * Wq[c,e] ----
    {
        float4 a = make_float4(0.f, 0.f, 0.f, 0.f);
#pragma unroll
        for (int ci = 0; ci < 4; ++ci) {
            int c = hw * 4 + ci;
            float s = squ[c];
            float4 v = ((const float4*)Wq)[c * 16 + l16];
            a.x += s * v.x; a.y += s * v.y; a.z += s * v.z; a.w += s * v.w;
        }
        ((float4*)spart)[hw * 16 + l16] = a;
    }
    __syncthreads();
    if (tid < DD) {
        float s = 0.f;
#pragma unroll
        for (int i = 0; i < 16; ++i) s += spart[i * DD + tid];
        stmp[tid] = s;
    }
    __syncthreads();

    // ---- u[row] = sum_e tmp[e] * Wk[row,e]  (half-warp per row) ----
    {
        float4 tv = ((const float4*)stmp)[l16];
#pragma unroll
        for (int r = 0; r < 4; ++r) {
            int row = hw + 16 * r;
            float4 wv = ((const float4*)(Wk + row * DD))[l16];
            float p = wv.x * tv.x + wv.y * tv.y + wv.z * tv.z + wv.w * tv.w;
#pragma unroll
            for (int o = 8; o; o >>= 1)
                p += __shfl_xor_sync(0xffffffffu, p, o);
            if (l16 == 0) su[row] = p;
        }
    }

    // ---- wait for full k tile, then wait-free smem compute ----
    cp_wait_all();
    __syncthreads();

    const int   len   = kes_length[b];
    const float biasD = bias[0] * (float)DD;
    const float mfill = (len == 0) ? 1.f : 0.f;
    const float4 uv   = ((const float4*)su)[l16];
    const float4* kb4 = (const float4*)kbuf;
    const int rbase   = warp * RPW;

    float4 wa   = make_float4(0.f, 0.f, 0.f, 0.f);
    float  esum = 0.f;

#pragma unroll
    for (int i = 0; i < 13; ++i) {
        int  rl    = 2 * i + half;                 // 0..25 ; 25 invalid
        bool valid = (rl < RPW);
        int  r     = rbase + (valid ? rl : 0);
        float4 kv  = kb4[r * 16 + l16];
        float pd = kv.x * uv.x + kv.y * uv.y + kv.z * uv.z + kv.w * uv.w;
#pragma unroll
        for (int o = 8; o; o >>= 1)
            pd += __shfl_xor_sync(0xffffffffu, pd, o);   // within half-warp
        float e = 0.f;
        if (valid)
            e = (rbase + rl < len) ? fast_exp8(fast_sigmoid(pd + biasD)) : mfill;
        wa.x += e * kv.x; wa.y += e * kv.y;
        wa.z += e * kv.z; wa.w += e * kv.w;
        esum += e;
    }

    // ---- join + cross-half-warp reduce ----
    __syncthreads();
    ((float4*)spart)[hw * 16 + l16] = wa;
    if (l16 == 0) swr[hw] = esum;
    __syncthreads();

    if (tid < DD) {
        float s = 0.f;
#pragma unroll
        for (int i = 0; i < 16; ++i) s += spart[i * DD + tid];
        su[tid] = s;
    }
    __syncthreads();

    // ---- out[b,e] = inv * sum_c w[c] * Wv[c,e] ----
    {
        float4 a = make_float4(0.f, 0.f, 0.f, 0.f);
#pragma unroll
        for (int ci = 0; ci < 4; ++ci) {
            int c = hw * 4 + ci;
            float s = su[c];
            float4 v = ((const float4*)Wv)[c * 16 + l16];
            a.x += s * v.x; a.y += s * v.y; a.z += s * v.z; a.w += s * v.w;
        }
        ((float4*)spart)[hw * 16 + l16] = a;
    }
    __syncthreads();
    if (tid < DD) {
        float tot = 0.f;
#pragma unroll
        for (int i = 0; i < 16; ++i) tot += swr[i];
        float s = 0.f;
#pragma unroll
        for (int i = 0; i < 16; ++i) s += spart[i * DD + tid];
        out[(size_t)b * DD + tid] = s * (1.f / tot);
    }
}

extern "C" void kernel_launch(void* const* d_in, const int* in_sizes, int n_in,
                              void* d_out, int out_size) {
    const float* q    = (const float*)d_in[0];
    const float* k    = (const float*)d_in[1];
    // d_in[2] = v : unused by the reference computation
    const int*   kes  = (const int*)  d_in[3];
    const float* fs   = (const float*)d_in[4];
    const float* bias = (const float*)d_in[5];
    const float* Wq   = (const float*)d_in[6];
    const float* Wk   = (const float*)d_in[7];
    const float* Wv   = (const float*)d_in[8];
    float*       out  = (float*)d_out;

    cudaFuncSetAttribute(attn_kernel, cudaFuncAttributePreferredSharedMemoryCarveout, 100);
    cudaFuncSetAttribute(attn_kernel, cudaFuncAttributeMaxDynamicSharedMemorySize, SMEM_BYTES);
    attn_kernel<<<BB, NT, SMEM_BYTES>>>(q, k, kes, fs, bias, Wq, Wk, Wv, out);
}

// round 9
// speedup vs baseline: 1.0094x; 1.0094x over previous
#include <cuda_runtime.h>
#include <cstdint>

#define BB      1024
#define MAXLEN  200
#define FF      64
#define DD      64
#define NT      256
#define RPW     25                         // rows per warp in k2
#define KUNITS  ((MAXLEN * DD * 4) / 16)   // 3200 16-byte units per k tile
#define SMEM2_FLOATS (MAXLEN * DD + 16 * DD + DD + 16)
#define SMEM2_BYTES  (SMEM2_FLOATS * 4)

__device__ float g_u[BB * DD];             // 256 KB scratch: u per batch

__device__ __forceinline__ void cp_async16(uint32_t saddr, const void* gaddr) {
    asm volatile("cp.async.cg.shared.global [%0], [%1], 16;" :: "r"(saddr), "l"(gaddr) : "memory");
}
__device__ __forceinline__ void cp_commit() {
    asm volatile("cp.async.commit_group;" ::: "memory");
}
__device__ __forceinline__ void cp_wait_all() {
    asm volatile("cp.async.wait_group 0;" ::: "memory");
}
__device__ __forceinline__ float fast_sigmoid(float x) {
    float t;
    asm("tanh.approx.f32 %0, %1;" : "=f"(t) : "f"(0.5f * x));
    return fmaf(0.5f, t, 0.5f);
}
__device__ __forceinline__ float fast_exp8(float x) {   // exp(x/8)
    float e;
    asm("ex2.approx.f32 %0, %1;" : "=f"(e) : "f"(x * 0.18033688011112042f));
    return e;
}

// ================= Kernel 1: u[b] = ((fs.q[b]) @ Wq) @ Wk^T =================
__global__ __launch_bounds__(NT, 8)
void u_kernel(const float* __restrict__ q,
              const float* __restrict__ fs,
              const float* __restrict__ Wq,
              const float* __restrict__ Wk) {
    __shared__ float spart[16 * DD];
    __shared__ float squ[DD];
    __shared__ float stmp[DD];

    const int b   = blockIdx.x;
    const int tid = threadIdx.x;
    const int hw  = tid >> 4;
    const int l16 = tid & 15;

    // qbar[d] = sum_f fs[f] * q[b,f,d]  (float4, 16-way f split)
    {
        const float4* qb4 = (const float4*)(q + (size_t)b * FF * DD);
        float4 a = make_float4(0.f, 0.f, 0.f, 0.f);
#pragma unroll
        for (int fi = 0; fi < 4; ++fi) {
            int f = hw + 16 * fi;
            float s = fs[f];
            float4 v = qb4[f * 16 + l16];
            a.x += s * v.x; a.y += s * v.y; a.z += s * v.z; a.w += s * v.w;
        }
        ((float4*)spart)[hw * 16 + l16] = a;
    }
    __syncthreads();
    if (tid < DD) {
        float s = 0.f;
#pragma unroll
        for (int i = 0; i < 16; ++i) s += spart[i * DD + tid];
        squ[tid] = s;
    }
    __syncthreads();

    // tmp[e] = sum_c qbar[c] * Wq[c,e]
    {
        float4 a = make_float4(0.f, 0.f, 0.f, 0.f);
#pragma unroll
        for (int ci = 0; ci < 4; ++ci) {
            int c = hw * 4 + ci;
            float s = squ[c];
            float4 v = ((const float4*)Wq)[c * 16 + l16];
            a.x += s * v.x; a.y += s * v.y; a.z += s * v.z; a.w += s * v.w;
        }
        ((float4*)spart)[hw * 16 + l16] = a;
    }
    __syncthreads();
    if (tid < DD) {
        float s = 0.f;
#pragma unroll
        for (int i = 0; i < 16; ++i) s += spart[i * DD + tid];
        stmp[tid] = s;
    }
    __syncthreads();

    // u[row] = sum_e tmp[e] * Wk[row,e]  (half-warp per row) -> global
    {
        float4 tv = ((const float4*)stmp)[l16];
#pragma unroll
        for (int r = 0; r < 4; ++r) {
            int row = hw + 16 * r;
            float4 wv = ((const float4*)(Wk + row * DD))[l16];
            float p = wv.x * tv.x + wv.y * tv.y + wv.z * tv.z + wv.w * tv.w;
#pragma unroll
            for (int o = 8; o; o >>= 1)
                p += __shfl_xor_sync(0xffffffffu, p, o);
            if (l16 == 0) g_u[b * DD + row] = p;
        }
    }
}

// ============ Kernel 2: stream k, score/softmax/weighted-sum, epilogue ============
__global__ __launch_bounds__(NT, 4)
void score_kernel(const float* __restrict__ k,
                  const int*   __restrict__ kes_length,
                  const float* __restrict__ bias,
                  const float* __restrict__ Wv,
                  float*       __restrict__ out) {
    extern __shared__ float smd[];
    float* kbuf  = smd;                    // 12800 floats : full k tile
    float* spart = kbuf + MAXLEN * DD;     // 16*64 partials
    float* su    = spart + 16 * DD;        // w
    float* swr   = su + DD;                // 16 exp-sums

    const int b    = blockIdx.x;
    const int tid  = threadIdx.x;
    const int lane = tid & 31;
    const int warp = tid >> 5;
    const int half = lane >> 4;
    const int hw   = tid >> 4;
    const int l16  = tid & 15;

    // ---- stage ENTIRE k[b] tile: one burst, nothing in between ----
    {
        const uint32_t sbk = (uint32_t)__cvta_generic_to_shared(kbuf);
        const char* gk = (const char*)(k + (size_t)b * MAXLEN * DD);
#pragma unroll
        for (int r = 0; r < 12; ++r) {
            int u = tid + r * NT;
            cp_async16(sbk + u * 16, gk + (size_t)u * 16);
        }
        if (tid < KUNITS - 12 * NT)
            cp_async16(sbk + (tid + 12 * NT) * 16, gk + (size_t)(tid + 12 * NT) * 16);
        cp_commit();
    }

    // tiny loads (L2-resident u, len, bias) — only non-DMA global traffic
    const float4 uv   = ((const float4*)(g_u + b * DD))[l16];
    const int    len  = kes_length[b];
    const float biasD = bias[0] * (float)DD;
    const float mfill = (len == 0) ? 1.f : 0.f;

    cp_wait_all();
    __syncthreads();

    const float4* kb4 = (const float4*)kbuf;
    const int rbase   = warp * RPW;

    float4 wa   = make_float4(0.f, 0.f, 0.f, 0.f);
    float  esum = 0.f;

#pragma unroll
    for (int i = 0; i < 13; ++i) {
        int  rl    = 2 * i + half;                 // 0..25 ; 25 invalid
        bool valid = (rl < RPW);
        int  r     = rbase + (valid ? rl : 0);
        float4 kv  = kb4[r * 16 + l16];
        float pd = kv.x * uv.x + kv.y * uv.y + kv.z * uv.z + kv.w * uv.w;
#pragma unroll
        for (int o = 8; o; o >>= 1)
            pd += __shfl_xor_sync(0xffffffffu, pd, o);   // within half-warp
        float e = 0.f;
        if (valid)
            e = (rbase + rl < len) ? fast_exp8(fast_sigmoid(pd + biasD)) : mfill;
        wa.x += e * kv.x; wa.y += e * kv.y;
        wa.z += e * kv.z; wa.w += e * kv.w;
        esum += e;
    }

    ((float4*)spart)[hw * 16 + l16] = wa;
    if (l16 == 0) swr[hw] = esum;
    __syncthreads();

    if (tid < DD) {
        float s = 0.f;
#pragma unroll
        for (int i = 0; i < 16; ++i) s += spart[i * DD + tid];
        su[tid] = s;
    }
    __syncthreads();

    // out[b,e] = inv * sum_c w[c] * Wv[c,e]
    {
        float4 a = make_float4(0.f, 0.f, 0.f, 0.f);
#pragma unroll
        for (int ci = 0; ci < 4; ++ci) {
            int c = hw * 4 + ci;
            float s = su[c];
            float4 v = ((const float4*)Wv)[c * 16 + l16];
            a.x += s * v.x; a.y += s * v.y; a.z += s * v.z; a.w += s * v.w;
        }
        ((float4*)spart)[hw * 16 + l16] = a;
    }
    __syncthreads();
    if (tid < DD) {
        float tot = 0.f;
#pragma unroll
        for (int i = 0; i < 16; ++i) tot += swr[i];
        float s = 0.f;
#pragma unroll
        for (int i = 0; i < 16; ++i) s += spart[i * DD + tid];
        out[(size_t)b * DD + tid] = s * (1.f / tot);
    }
}

extern "C" void kernel_launch(void* const* d_in, const int* in_sizes, int n_in,
                              void* d_out, int out_size) {
    const float* q    = (const float*)d_in[0];
    const float* k    = (const float*)d_in[1];
    // d_in[2] = v : unused by the reference computation
    const int*   kes  = (const int*)  d_in[3];
    const float* fs   = (const float*)d_in[4];
    const float* bias = (const float*)d_in[5];
    const float* Wq   = (const float*)d_in[6];
    const float* Wk   = (const float*)d_in[7];
    const float* Wv   = (const float*)d_in[8];
    float*       out  = (float*)d_out;

    cudaFuncSetAttribute(score_kernel, cudaFuncAttributePreferredSharedMemoryCarveout, 100);
    cudaFuncSetAttribute(score_kernel, cudaFuncAttributeMaxDynamicSharedMemorySize, SMEM2_BYTES);

    u_kernel<<<BB, NT>>>(q, fs, Wq, Wk);
    score_kernel<<<BB, NT, SMEM2_BYTES>>>(k, kes, bias, Wv, out);
}